// round 1
// baseline (speedup 1.0000x reference)
#include <cuda_runtime.h>
#include <math.h>

// EyesMouthLoss: mean(|pred-target| * (1 + priority*299))
// priority(b,y,x) = clip(eye(b,y,x) + mouth(b,y,x), 0, 1)
// eye   = max over landmarks 36..47 of clip(1 - dist/15, 0, 1)
// mouth = max over landmarks 48..67 of clip(1 - dist/15, 0, 1)
//
// Key algebra: max_j clip(1 - d_j/R) == clip(1 - sqrt(min_j d_j^2)/R)
// Key pruning: a landmark only matters on rows with (y-cy)^2 < R^2.

#define H 512
#define W 512
#define C 3
#define B 16
#define RADIUS2 225.0f
#define INV_R (1.0f / 15.0f)
#define N_TOTAL ((double)B * C * H * W)

__device__ double g_acc;

__global__ void eml_init() { g_acc = 0.0; }

__global__ void __launch_bounds__(128) eml_main(
    const float* __restrict__ pred,
    const float* __restrict__ target,
    const int*   __restrict__ lm)
{
    // one block per (batch, row)
    const int row = blockIdx.x;          // b*H + y
    const int b   = row >> 9;
    const int y   = row & (H - 1);
    const int tid = threadIdx.x;

    __shared__ float s_ecx[12], s_ed2[12];
    __shared__ float s_mcx[20], s_md2[20];
    __shared__ int   s_ne, s_nm;
    __shared__ float s_part[4];

    if (tid == 0) { s_ne = 0; s_nm = 0; }
    __syncthreads();

    // prescan: threads 36..67 each own one landmark; keep row-active ones
    if (tid >= 36 && tid < 68) {
        const int lx = lm[b * 136 + tid * 2 + 0];
        const int ly = lm[b * 136 + tid * 2 + 1];
        const float cx = fminf(fmaxf((float)lx, 0.0f), (float)(W - 1));
        const float cy = fminf(fmaxf((float)ly, 0.0f), (float)(H - 1));
        const float dy  = (float)y - cy;
        const float dy2 = dy * dy;
        if (dy2 < RADIUS2) {
            if (tid < 48) { int k = atomicAdd(&s_ne, 1); s_ecx[k] = cx; s_ed2[k] = dy2; }
            else          { int k = atomicAdd(&s_nm, 1); s_mcx[k] = cx; s_md2[k] = dy2; }
        }
    }
    __syncthreads();

    const int ne = s_ne;
    const int nm = s_nm;

    // each thread handles 4 consecutive pixels (float4) x 3 channels
    const int x0 = tid << 2;

    float wgt[4];
#pragma unroll
    for (int k = 0; k < 4; k++) {
        const float xf = (float)(x0 + k);
        float emn = 3.0e8f, mmn = 3.0e8f;
        for (int j = 0; j < ne; j++) {
            const float dx = xf - s_ecx[j];
            emn = fminf(emn, fmaf(dx, dx, s_ed2[j]));
        }
        for (int j = 0; j < nm; j++) {
            const float dx = xf - s_mcx[j];
            mmn = fminf(mmn, fmaf(dx, dx, s_md2[j]));
        }
        const float e = (emn < RADIUS2) ? (1.0f - sqrtf(emn) * INV_R) : 0.0f;
        const float m = (mmn < RADIUS2) ? (1.0f - sqrtf(mmn) * INV_R) : 0.0f;
        const float p = fminf(e + m, 1.0f);
        wgt[k] = fmaf(p, 299.0f, 1.0f);
    }

    const size_t rowbase = (size_t)b * (C * H * W) + (size_t)y * W + x0;
    float acc = 0.0f;
#pragma unroll
    for (int c = 0; c < C; c++) {
        const size_t off = rowbase + (size_t)c * (H * W);
        const float4 pv = *reinterpret_cast<const float4*>(pred + off);
        const float4 tv = *reinterpret_cast<const float4*>(target + off);
        acc = fmaf(fabsf(pv.x - tv.x), wgt[0], acc);
        acc = fmaf(fabsf(pv.y - tv.y), wgt[1], acc);
        acc = fmaf(fabsf(pv.z - tv.z), wgt[2], acc);
        acc = fmaf(fabsf(pv.w - tv.w), wgt[3], acc);
    }

    // warp reduce
#pragma unroll
    for (int s = 16; s > 0; s >>= 1)
        acc += __shfl_xor_sync(0xFFFFFFFFu, acc, s);

    if ((tid & 31) == 0) s_part[tid >> 5] = acc;
    __syncthreads();

    if (tid == 0) {
        const float blocksum = s_part[0] + s_part[1] + s_part[2] + s_part[3];
        atomicAdd(&g_acc, (double)blocksum);
    }
}

__global__ void eml_fin(float* out) {
    out[0] = (float)(g_acc / N_TOTAL);
}

extern "C" void kernel_launch(void* const* d_in, const int* in_sizes, int n_in,
                              void* d_out, int out_size)
{
    const float* pred   = (const float*)d_in[0];
    const float* target = (const float*)d_in[1];
    const int*   lmk    = (const int*)d_in[2];
    float* out = (float*)d_out;

    eml_init<<<1, 1>>>();
    eml_main<<<B * H, 128>>>(pred, target, lmk);
    eml_fin<<<1, 1>>>(out);
}